// round 1
// baseline (speedup 1.0000x reference)
#include <cuda_runtime.h>
#include <math.h>

#define BB 1024
#define NN 32
#define DOBS 17
#define DACT 6
#define DIN 23
#define HH 256
#define NSTEPS 5

// Transposed W2 for coalesced backward reads (scratch: __device__ global, no alloc)
__device__ float g_W2T[2][HH * HH];

__global__ void transpose_w2(const float* __restrict__ w2a,
                             const float* __restrict__ w2b) {
    int j = blockIdx.x;   // 0..255
    int k = threadIdx.x;  // 0..255
    g_W2T[0][j * HH + k] = w2a[k * HH + j];
    g_W2T[1][j * HH + k] = w2b[k * HH + j];
}

__global__ __launch_bounds__(256, 2) void svgd_kernel(
    const float* __restrict__ obs, const float* __restrict__ a0,
    const float* __restrict__ W1a, const float* __restrict__ B1a,
    const float* __restrict__ W2a, const float* __restrict__ B2a,
    const float* __restrict__ W3a, const float* __restrict__ B3a,
    const float* __restrict__ W1b, const float* __restrict__ B1b,
    const float* __restrict__ W2b, const float* __restrict__ B2b,
    const float* __restrict__ W3b, const float* __restrict__ B3b,
    float* __restrict__ out)
{
    __shared__ __align__(16) float s_h[NN * HH];   // 32 KB: h1 / dh2 / dh1 / sort scratch
    __shared__ float s_x[NN * 32];                 // input rows (obs | act), padded stride 32
    __shared__ float s_d2[NN * NN];
    __shared__ float s_K[NN * NN];
    __shared__ float s_q[2][NN];
    __shared__ __align__(16) float s_s[NN * 8];    // score, padded stride 8
    __shared__ float s_a[NN * 8];                  // actions, padded stride 8
    __shared__ float s_logp[NN];
    __shared__ float s_lpn[NN];
    __shared__ float s_red[8 * NN];
    __shared__ float s_gate[NN];

    const int b = blockIdx.x;
    const int tid = threadIdx.x;
    const int lane = tid & 31;
    const int warp = tid >> 5;

    // Load obs + a0
    for (int idx = tid; idx < NN * DOBS; idx += 256) {
        int n = idx / DOBS, k = idx % DOBS;
        s_x[n * 32 + k] = obs[(b * NN + n) * DOBS + k];
    }
    for (int idx = tid; idx < NN * DACT; idx += 256) {
        int n = idx / DACT, d = idx % DACT;
        s_a[n * 8 + d] = a0[(b * NN + n) * DACT + d];
    }
    if (tid < NN) s_logp[tid] = 0.0f;
    __syncthreads();
    if (tid < NN) {
        float ss = 0.0f;
        #pragma unroll
        for (int d = 0; d < DACT; d++) { float v = s_a[tid * 8 + d]; ss += v * v; }
        s_lpn[tid] = -3.0f * logf(6.283185307179586f * 0.3f) - (0.5f / 0.3f) * ss;
    }

    for (int step = 0; step < NSTEPS; ++step) {
        __syncthreads();
        for (int idx = tid; idx < NN * DACT; idx += 256) {
            int n = idx / DACT, d = idx % DACT;
            s_x[n * 32 + DOBS + d] = s_a[n * 8 + d];
        }
        for (int idx = tid; idx < NN * 8; idx += 256) s_s[idx] = 0.0f;
        __syncthreads();

        unsigned m1[2], m2[2];

        // ---------------- forward both Q nets ----------------
        for (int net = 0; net < 2; ++net) {
            const float* W1 = net ? W1b : W1a;
            const float* B1 = net ? B1b : B1a;
            const float* W2 = net ? W2b : W2a;
            const float* B2 = net ? B2b : B2a;
            const float* W3 = net ? W3b : W3a;
            const float* B3 = net ? B3b : B3a;

            // layer1: thread j computes h1[n][j] for all n
            float c[DIN];
            #pragma unroll
            for (int k = 0; k < DIN; k++) c[k] = W1[k * HH + tid];
            float bb1 = B1[tid];
            unsigned mm1 = 0;
            for (int n = 0; n < NN; n++) {
                float z = bb1;
                #pragma unroll
                for (int k = 0; k < DIN; k++) z += s_x[n * 32 + k] * c[k];
                if (z > 0.0f) mm1 |= (1u << n); else z = 0.0f;
                s_h[n * HH + tid] = z;
            }
            m1[net] = mm1;
            __syncthreads();

            // layer2 + fused q partials
            float acc[NN];
            #pragma unroll
            for (int n = 0; n < NN; n++) acc[n] = 0.0f;
            for (int kb = 0; kb < HH; kb += 4) {
                float w0 = W2[(kb + 0) * HH + tid];
                float w1 = W2[(kb + 1) * HH + tid];
                float w2 = W2[(kb + 2) * HH + tid];
                float w3 = W2[(kb + 3) * HH + tid];
                #pragma unroll
                for (int n = 0; n < NN; n++) {
                    float4 h4 = *(const float4*)&s_h[n * HH + kb];
                    acc[n] += h4.x * w0 + h4.y * w1 + h4.z * w2 + h4.w * w3;
                }
            }
            float bb2 = B2[tid], w3v = W3[tid];
            unsigned mm2 = 0;
            #pragma unroll
            for (int n = 0; n < NN; n++) {
                float z = acc[n] + bb2;
                if (z > 0.0f) { mm2 |= (1u << n); acc[n] = z * w3v; }
                else acc[n] = 0.0f;
            }
            m2[net] = mm2;

            // block-reduce acc[n] -> q[n]
            #pragma unroll
            for (int n = 0; n < NN; n++) {
                float v = acc[n];
                v += __shfl_xor_sync(0xffffffffu, v, 16);
                v += __shfl_xor_sync(0xffffffffu, v, 8);
                v += __shfl_xor_sync(0xffffffffu, v, 4);
                v += __shfl_xor_sync(0xffffffffu, v, 2);
                v += __shfl_xor_sync(0xffffffffu, v, 1);
                if (lane == 0) s_red[warp * NN + n] = v;
            }
            __syncthreads();
            if (tid < NN) {
                float q = B3[0];
                #pragma unroll
                for (int w = 0; w < 8; w++) q += s_red[w * NN + tid];
                s_q[net][tid] = q;
            }
            __syncthreads();
        }

        if (tid < NN) s_gate[tid] = (s_q[0][tid] <= s_q[1][tid]) ? 1.0f : 0.0f;
        __syncthreads();

        // ---------------- backward both Q nets (input grad only) ----------------
        for (int net = 0; net < 2; ++net) {
            const float* W1 = net ? W1b : W1a;
            const float* W3 = net ? W3b : W3a;
            float w3v = W3[tid];
            unsigned mm2 = m2[net], mm1 = m1[net];

            // dh2[n][j] = gate[n]*W3[j]*mask2
            for (int n = 0; n < NN; n++) {
                float g = net ? (1.0f - s_gate[n]) : s_gate[n];
                s_h[n * HH + tid] = ((mm2 >> n) & 1u) ? g * w3v : 0.0f;
            }
            __syncthreads();

            // dh1[n][k] = sum_j dh2[n][j] * W2T[j][k]  (coalesced)
            float acc[NN];
            #pragma unroll
            for (int n = 0; n < NN; n++) acc[n] = 0.0f;
            const float* W2T = g_W2T[net];
            for (int jb = 0; jb < HH; jb += 4) {
                float w0 = W2T[(jb + 0) * HH + tid];
                float w1 = W2T[(jb + 1) * HH + tid];
                float w2 = W2T[(jb + 2) * HH + tid];
                float w3 = W2T[(jb + 3) * HH + tid];
                #pragma unroll
                for (int n = 0; n < NN; n++) {
                    float4 d4 = *(const float4*)&s_h[n * HH + jb];
                    acc[n] += d4.x * w0 + d4.y * w1 + d4.z * w2 + d4.w * w3;
                }
            }
            __syncthreads();  // all dh2 reads done before overwrite
            for (int n = 0; n < NN; n++)
                s_h[n * HH + tid] = ((mm1 >> n) & 1u) ? acc[n] : 0.0f;
            __syncthreads();

            // da[n][d] = sum_k dh1[n][k] * W1[17+d][k], accumulate (gated) into s_s
            if (tid < NN * DACT) {
                int n = tid / DACT, d = tid % DACT;
                const float* w1r = W1 + (DOBS + d) * HH;
                float sum = 0.0f;
                for (int k = 0; k < HH; k += 4) {
                    float4 h4 = *(const float4*)&s_h[n * HH + k];
                    float4 w4 = *(const float4*)&w1r[k];
                    sum += h4.x * w4.x + h4.y * w4.y + h4.z * w4.z + h4.w * w4.w;
                }
                s_s[n * 8 + d] += sum;
            }
            __syncthreads();
        }

        // ---------------- SVGD update ----------------
        // pairwise squared distances
        for (int p = tid; p < NN * NN; p += 256) {
            int i = p >> 5, j = p & 31;
            float ds = 0.0f;
            #pragma unroll
            for (int d = 0; d < DACT; d++) {
                float df = s_a[i * 8 + d] - s_a[j * 8 + d];
                ds += df * df;
            }
            s_d2[p] = ds;
            s_h[p] = ds;  // sort copy
        }
        __syncthreads();

        // bitonic sort of 1024 values (for exact median)
        for (int ks = 2; ks <= NN * NN; ks <<= 1) {
            for (int jj = ks >> 1; jj > 0; jj >>= 1) {
                #pragma unroll
                for (int e = 0; e < 4; e++) {
                    int idx = (e << 8) | tid;
                    int ixj = idx ^ jj;
                    if (ixj > idx) {
                        float va = s_h[idx], vb = s_h[ixj];
                        bool up = ((idx & ks) == 0);
                        if ((va > vb) == up) { s_h[idx] = vb; s_h[ixj] = va; }
                    }
                }
                __syncthreads();
            }
        }

        float med = 0.5f * (s_h[511] + s_h[512]);
        float hm = med / logf(33.0f);
        float gamma = 1.0f / (2.0f * hm + 1e-8f);
        for (int p = tid; p < NN * NN; p += 256)
            s_K[p] = expf(-gamma * s_d2[p]);
        __syncthreads();

        float anew[DACT];
        float lpdelta = 0.0f;
        if (tid < NN) {
            int i = tid;
            float ai[DACT];
            #pragma unroll
            for (int d = 0; d < DACT; d++) ai[d] = s_a[i * 8 + d];
            float ph[DACT] = {0, 0, 0, 0, 0, 0};
            float t1 = 0.0f, t2s = 0.0f;
            for (int j = 0; j < NN; j++) {
                float Kij = s_K[i * 32 + j];
                float dot = 0.0f;
                #pragma unroll
                for (int d = 0; d < DACT; d++) {
                    float df = ai[d] - s_a[j * 8 + d];
                    float sj = s_s[j * 8 + d];
                    dot += df * sj;
                    ph[d] += Kij * sj + 2.0f * gamma * Kij * df;
                }
                t1 += -2.0f * gamma * Kij * dot;
                float I = (i == j) ? 1.0f : 0.0f;
                t2s += 2.0f * gamma * Kij * s_d2[i * 32 + j] - 6.0f * (Kij - I);
            }
            t1 *= (1.0f / 31.0f);
            float t2 = -2.0f * gamma * t2s * (1.0f / 31.0f);
            lpdelta = 0.05f * (t1 + t2);
            #pragma unroll
            for (int d = 0; d < DACT; d++)
                anew[d] = ai[d] + 0.05f * ph[d] * (1.0f / 32.0f);
        }
        __syncthreads();
        if (tid < NN) {
            s_logp[tid] -= lpdelta;
            #pragma unroll
            for (int d = 0; d < DACT; d++) s_a[tid * 8 + d] = anew[d];
        }
        __syncthreads();
    }

    // ---------------- finalize ----------------
    __syncthreads();
    if (tid < NN) {
        int n = tid;
        float lpt = 0.0f;
        #pragma unroll
        for (int d = 0; d < DACT; d++) {
            float av = s_a[n * 8 + d];
            float x = -2.0f * av;
            float sp = (x > 0.0f) ? (x + log1pf(expf(-x))) : log1pf(expf(x));
            lpt += -2.0f * (0.6931471805599453f - av - sp);
            out[(b * NN + n) * DACT + d] = tanhf(av);
        }
        s_red[n] = s_lpn[n] + s_logp[n] + lpt;
    }
    __syncthreads();
    if (tid == 0) {
        float m = 0.0f;
        for (int n = 0; n < NN; n++) m += s_red[n];
        out[BB * NN * DACT + b] = m * (1.0f / 32.0f);
    }
}

extern "C" void kernel_launch(void* const* d_in, const int* in_sizes, int n_in,
                              void* d_out, int out_size) {
    const float* obs  = (const float*)d_in[0];
    const float* a0   = (const float*)d_in[1];
    const float* q1W1 = (const float*)d_in[2];
    const float* q1b1 = (const float*)d_in[3];
    const float* q1W2 = (const float*)d_in[4];
    const float* q1b2 = (const float*)d_in[5];
    const float* q1W3 = (const float*)d_in[6];
    const float* q1b3 = (const float*)d_in[7];
    const float* q2W1 = (const float*)d_in[8];
    const float* q2b1 = (const float*)d_in[9];
    const float* q2W2 = (const float*)d_in[10];
    const float* q2b2 = (const float*)d_in[11];
    const float* q2W3 = (const float*)d_in[12];
    const float* q2b3 = (const float*)d_in[13];
    float* out = (float*)d_out;

    transpose_w2<<<HH, HH>>>(q1W2, q2W2);
    svgd_kernel<<<BB, 256>>>(obs, a0,
                             q1W1, q1b1, q1W2, q1b2, q1W3, q1b3,
                             q2W1, q2b1, q2W2, q2b2, q2W3, q2b3,
                             out);
}